// round 5
// baseline (speedup 1.0000x reference)
#include <cuda_runtime.h>
#include <cuda_bf16.h>
#include <cstdint>

// ============================================================================
// CESLayer: out[b,o] = cos( x@angle^T + bias ) * exp( x@log|w|^T )
// B=262144, I=O=128.  mma.sync bf16 with hi/lo split (xh*Wh + xl*Wh + xh*Wl).
// R5: intra-warp pipeline — next tile's x LDGs issued after k-loop (latency
//     hidden under epilogue); split+STS at loop top; bias folded into acc init.
// ============================================================================

#define N_TILES   4096            // 64-row tiles
#define GRID_CTAS 148
#define TILE_STRIDE (2 * GRID_CTAS)
#define LDS_STRIDE 136            // bf16 elems per smem row (128+8 pad)

// smem byte offsets
// group g X: [g*34816, g*34816+17408) hi, +17408 lo   (64 rows x 136 x bf16)
#define OFF_W    69632u           // 4 mats * 34816: [logH, logL, angH, angL]
#define OFF_BIAS 208896u
#define SMEM_BYTES 209664u

__device__ __align__(16) __nv_bfloat16 g_W[4 * 16384];

// ---------------------------------------------------------------------------
__device__ __forceinline__ uint32_t smem_u32(const void* p) {
    uint32_t a;
    asm("{ .reg .u64 t; cvta.to.shared.u64 t, %1; cvt.u32.u64 %0, t; }"
        : "=r"(a) : "l"(p));
    return a;
}

__device__ __forceinline__ uint32_t b2u(__nv_bfloat162 v) {
    return *reinterpret_cast<uint32_t*>(&v);
}

__device__ __forceinline__ void ldsm_x4(uint32_t r[4], uint32_t addr) {
    asm volatile("ldmatrix.sync.aligned.m8n8.x4.shared.b16 {%0,%1,%2,%3}, [%4];"
                 : "=r"(r[0]), "=r"(r[1]), "=r"(r[2]), "=r"(r[3]) : "r"(addr));
}

__device__ __forceinline__ void mma16816(float c[4], const uint32_t a[4],
                                         uint32_t b0, uint32_t b1) {
    asm volatile(
        "mma.sync.aligned.m16n8k16.row.col.f32.bf16.bf16.f32 "
        "{%0,%1,%2,%3}, {%4,%5,%6,%7}, {%8,%9}, {%0,%1,%2,%3};"
        : "+f"(c[0]), "+f"(c[1]), "+f"(c[2]), "+f"(c[3])
        : "r"(a[0]), "r"(a[1]), "r"(a[2]), "r"(a[3]), "r"(b0), "r"(b1));
}

// volatile LDG.128 — ordered w.r.t. the volatile mma asm, so these stay AFTER
// the k-loop (issued under the epilogue, consumed next iteration).
__device__ __forceinline__ void ldg128v(float4& v, const float* p) {
    asm volatile("ld.global.nc.v4.f32 {%0,%1,%2,%3}, [%4];"
                 : "=f"(v.x), "=f"(v.y), "=f"(v.z), "=f"(v.w) : "l"(p));
}

#define GBAR(id) asm volatile("bar.sync %0, 128;" :: "r"(id) : "memory")

// ---------------------------------------------------------------------------
__global__ void ces_prep(const float* __restrict__ wr, const float* __restrict__ wi) {
    int idx = blockIdx.x * blockDim.x + threadIdx.x;
    if (idx >= 16384) return;
    float a = wr[idx], b = wi[idx];
    float la = 0.5f * logf(fmaf(a, a, b * b));
    float an = atan2f(b, a);
    __nv_bfloat16 lah = __float2bfloat16(la);
    __nv_bfloat16 lal = __float2bfloat16(la - __bfloat162float(lah));
    __nv_bfloat16 anh = __float2bfloat16(an);
    __nv_bfloat16 anl = __float2bfloat16(an - __bfloat162float(anh));
    g_W[0 * 16384 + idx] = lah;
    g_W[1 * 16384 + idx] = lal;
    g_W[2 * 16384 + idx] = anh;
    g_W[3 * 16384 + idx] = anl;
}

// ---------------------------------------------------------------------------
// 8 warps = 2 groups x 4 warps. Group tile: 64 rows x 128 cols.
// Within group: wm = lwid&1 (32 rows), wn = lwid>>1 (64 cols).
// ---------------------------------------------------------------------------
__global__ void __launch_bounds__(256, 1)
ces_main(const float* __restrict__ x, const float* __restrict__ bias,
         float* __restrict__ out) {
    extern __shared__ char smem[];
    const uint32_t sb = smem_u32(smem);
    const int tid  = threadIdx.x;
    const int lane = tid & 31;
    const int wid  = tid >> 5;
    const int g    = wid >> 2;        // group 0/1
    const int lwid = wid & 3;         // warp in group
    const int wm   = lwid & 1;
    const int wn   = lwid >> 1;

    // ---- copy W into padded smem, once (all 256 threads) ----
    for (int r = tid; r < 512; r += 256) {
        const uint4* src = (const uint4*)(g_W + r * 128);
        uint4* dst = (uint4*)(smem + OFF_W + ((uint32_t)(r >> 7) * 17408u +
                                              (uint32_t)(r & 127) * LDS_STRIDE) * 2u);
        #pragma unroll
        for (int j = 0; j < 16; ++j) dst[j] = src[j];
    }
    if (tid < 128) ((float*)(smem + OFF_BIAS))[tid] = bias[tid];
    __syncthreads();

    // per-thread bias pairs (tile-invariant)
    float bs0[8], bs1[8];
    {
        const float* sbias = (const float*)(smem + OFF_BIAS);
        #pragma unroll
        for (int nt = 0; nt < 8; ++nt) {
            int c = wn * 64 + nt * 8 + 2 * (lane & 3);
            bs0[nt] = sbias[c];
            bs1[nt] = sbias[c + 1];
        }
    }

    // ldmatrix per-thread byte offsets
    const uint32_t aoff = ((uint32_t)(wm * 32 + (lane & 15)) * LDS_STRIDE +
                           (uint32_t)((lane >> 4) * 8)) * 2u;
    const uint32_t boff = ((uint32_t)(wn * 64 + ((lane & 7) | ((lane & 16) >> 1))) * LDS_STRIDE +
                           (uint32_t)(lane & 8)) * 2u;

    const uint32_t xbase   = sb + (uint32_t)g * 34816u;
    const uint32_t abase_h = xbase + aoff;
    const uint32_t abase_l = xbase + 17408u + aoff;
    const uint32_t MI_STEP = 16u * LDS_STRIDE * 2u;

    const int xrow0 = lwid;           // rows lwid + 4*j  (64 rows, 128 threads)
    const int xcol  = lane * 4;
    const int bar_id = g + 1;

    // ---- prologue: prefetch first tile's x into registers ----
    float4 v[16];
    int tile = blockIdx.x * 2 + g;
    if (tile < N_TILES) {
        #pragma unroll
        for (int j = 0; j < 16; ++j) {
            size_t row = (size_t)tile * 64 + xrow0 + 4 * j;
            v[j] = __ldg((const float4*)(x + row * 128 + xcol));
        }
    }

    for (; tile < N_TILES; tile += TILE_STRIDE) {
        GBAR(bar_id);   // group's previous-tile ldsm done before X rewrite

        // ---- split prefetched x hi/lo, STS ----
        #pragma unroll
        for (int j = 0; j < 16; ++j) {
            int row = xrow0 + 4 * j;
            __nv_bfloat162 h0 = __float22bfloat162_rn(make_float2(v[j].x, v[j].y));
            __nv_bfloat162 h1 = __float22bfloat162_rn(make_float2(v[j].z, v[j].w));
            __nv_bfloat162 L0 = __float22bfloat162_rn(make_float2(
                v[j].x - __bfloat162float(h0.x), v[j].y - __bfloat162float(h0.y)));
            __nv_bfloat162 L1 = __float22bfloat162_rn(make_float2(
                v[j].z - __bfloat162float(h1.x), v[j].w - __bfloat162float(h1.y)));
            uint32_t off = ((uint32_t)row * LDS_STRIDE + (uint32_t)xcol) * 2u;
            asm volatile("st.shared.v2.b32 [%0], {%1,%2};"
                         :: "r"(xbase + off), "r"(b2u(h0)), "r"(b2u(h1)) : "memory");
            asm volatile("st.shared.v2.b32 [%0], {%1,%2};"
                         :: "r"(xbase + 17408u + off), "r"(b2u(L0)), "r"(b2u(L1)) : "memory");
        }
        GBAR(bar_id);

        // ---- accumulators: log = 0, ang = bias (folded) ----
        float acc[2][2][8][4];
        #pragma unroll
        for (int i = 0; i < 2; ++i)
            #pragma unroll
            for (int n = 0; n < 8; ++n) {
                #pragma unroll
                for (int q = 0; q < 4; ++q) acc[0][i][n][q] = 0.f;
                acc[1][i][n][0] = bs0[n];
                acc[1][i][n][1] = bs1[n];
                acc[1][i][n][2] = bs0[n];
                acc[1][i][n][3] = bs1[n];
            }

        // ---- fused k-loop: every fragment loaded once per k-step ----
        uint32_t ah[2][2][4], al[2][2][4];   // [buf][mi][4]
        ldsm_x4(ah[0][0], abase_h);
        ldsm_x4(ah[0][1], abase_h + MI_STEP);
        ldsm_x4(al[0][0], abase_l);
        ldsm_x4(al[0][1], abase_l + MI_STEP);

        #pragma unroll
        for (int k = 0; k < 8; ++k) {
            const int cur = k & 1, nxt = cur ^ 1;
            const uint32_t kb = (uint32_t)k * 32u;

            if (k < 7) {
                const uint32_t kn = kb + 32u;
                ldsm_x4(ah[nxt][0], abase_h + kn);
                ldsm_x4(ah[nxt][1], abase_h + MI_STEP + kn);
                ldsm_x4(al[nxt][0], abase_l + kn);
                ldsm_x4(al[nxt][1], abase_l + MI_STEP + kn);
            }

            // ---- group 1: hi-weights (logH, angH), xh then xl ----
            {
                uint32_t b[2][4][4];
                #pragma unroll
                for (int s = 0; s < 2; ++s) {
                    const uint32_t wb = sb + OFF_W + (uint32_t)(s * 2) * 34816u + boff + kb;
                    #pragma unroll
                    for (int np = 0; np < 4; ++np)
                        ldsm_x4(b[s][np], wb + (uint32_t)np * MI_STEP);
                }
                #pragma unroll
                for (int s = 0; s < 2; ++s)
                    #pragma unroll
                    for (int np = 0; np < 4; ++np) {
                        mma16816(acc[s][0][np * 2],     ah[cur][0], b[s][np][0], b[s][np][1]);
                        mma16816(acc[s][1][np * 2],     ah[cur][1], b[s][np][0], b[s][np][1]);
                        mma16816(acc[s][0][np * 2 + 1], ah[cur][0], b[s][np][2], b[s][np][3]);
                        mma16816(acc[s][1][np * 2 + 1], ah[cur][1], b[s][np][2], b[s][np][3]);
                    }
                #pragma unroll
                for (int s = 0; s < 2; ++s)
                    #pragma unroll
                    for (int np = 0; np < 4; ++np) {
                        mma16816(acc[s][0][np * 2],     al[cur][0], b[s][np][0], b[s][np][1]);
                        mma16816(acc[s][1][np * 2],     al[cur][1], b[s][np][0], b[s][np][1]);
                        mma16816(acc[s][0][np * 2 + 1], al[cur][0], b[s][np][2], b[s][np][3]);
                        mma16816(acc[s][1][np * 2 + 1], al[cur][1], b[s][np][2], b[s][np][3]);
                    }
            }

            // ---- group 2: lo-weights (logL, angL), xh only ----
            {
                uint32_t b[2][4][4];
                #pragma unroll
                for (int s = 0; s < 2; ++s) {
                    const uint32_t wb = sb + OFF_W + (uint32_t)(s * 2 + 1) * 34816u + boff + kb;
                    #pragma unroll
                    for (int np = 0; np < 4; ++np)
                        ldsm_x4(b[s][np], wb + (uint32_t)np * MI_STEP);
                }
                #pragma unroll
                for (int s = 0; s < 2; ++s)
                    #pragma unroll
                    for (int np = 0; np < 4; ++np) {
                        mma16816(acc[s][0][np * 2],     ah[cur][0], b[s][np][0], b[s][np][1]);
                        mma16816(acc[s][1][np * 2],     ah[cur][1], b[s][np][0], b[s][np][1]);
                        mma16816(acc[s][0][np * 2 + 1], ah[cur][0], b[s][np][2], b[s][np][3]);
                        mma16816(acc[s][1][np * 2 + 1], ah[cur][1], b[s][np][2], b[s][np][3]);
                    }
            }
        }

        // ---- prefetch next tile's x (volatile: stays after k-loop; latency
        //      hidden under the MUFU epilogue below) ----
        {
            int nxt_tile = tile + TILE_STRIDE;
            if (nxt_tile < N_TILES) {
                const float* base = x + (size_t)nxt_tile * 64 * 128;
                #pragma unroll
                for (int j = 0; j < 16; ++j)
                    ldg128v(v[j], base + (size_t)(xrow0 + 4 * j) * 128 + xcol);
            }
        }

        // ---- epilogue: out = cos(ang) * exp(log)   (bias already in ang) ----
        #pragma unroll
        for (int mt = 0; mt < 2; ++mt) {
            size_t r0 = (size_t)tile * 64 + wm * 32 + mt * 16 + (lane >> 2);
            float* p0 = out + r0 * 128 + wn * 64 + 2 * (lane & 3);
            #pragma unroll
            for (int nt = 0; nt < 8; ++nt) {
                const float* al_ = acc[1][mt][nt];
                const float* lg  = acc[0][mt][nt];
                float2 o0, o1;
                o0.x = __cosf(al_[0]) * __expf(lg[0]);
                o0.y = __cosf(al_[1]) * __expf(lg[1]);
                o1.x = __cosf(al_[2]) * __expf(lg[2]);
                o1.y = __cosf(al_[3]) * __expf(lg[3]);
                *(float2*)(p0 + nt * 8) = o0;
                *(float2*)(p0 + nt * 8 + 8 * 128) = o1;
            }
        }
    }
}

// ---------------------------------------------------------------------------
extern "C" void kernel_launch(void* const* d_in, const int* in_sizes, int n_in,
                              void* d_out, int out_size) {
    const float* x    = (const float*)d_in[0];
    const float* wr   = (const float*)d_in[1];
    const float* wi   = (const float*)d_in[2];
    const float* bias = (const float*)d_in[3];
    float* out = (float*)d_out;
    (void)in_sizes; (void)n_in; (void)out_size;

    cudaFuncSetAttribute(ces_main, cudaFuncAttributeMaxDynamicSharedMemorySize,
                         (int)SMEM_BYTES);

    ces_prep<<<64, 256>>>(wr, wi);
    ces_main<<<GRID_CTAS, 256, SMEM_BYTES>>>(x, bias, out);
}

// round 6
// speedup vs baseline: 1.0002x; 1.0002x over previous
#include <cuda_runtime.h>
#include <cuda_bf16.h>
#include <cstdint>

// ============================================================================
// CESLayer: out[b,o] = cos( x@angle^T + bias ) * exp( x@log|w|^T )
// B=262144, I=O=128.  mma.sync bf16 with hi/lo split (xh*Wh + xl*Wh + xh*Wl).
// R6: R4 base + group-1 startup stagger (~5000 cyc) to anti-phase the two
//     4-warp groups (one group's load/epilogue hides under the other's MMA),
//     + bias folded into accumulator init.
// ============================================================================

#define N_TILES   4096            // 64-row tiles
#define GRID_CTAS 148
#define LDS_STRIDE 136            // bf16 elems per smem row (128+8 pad)
#define STAGGER_CYC 5000ll

// smem byte offsets
// group g X: [g*34816, g*34816+17408) hi, +17408 lo   (64 rows x 136 x bf16)
#define OFF_W    69632u           // 4 mats * 34816: [logH, logL, angH, angL]
#define OFF_BIAS 208896u
#define SMEM_BYTES 209664u

__device__ __align__(16) __nv_bfloat16 g_W[4 * 16384];

// ---------------------------------------------------------------------------
__device__ __forceinline__ uint32_t smem_u32(const void* p) {
    uint32_t a;
    asm("{ .reg .u64 t; cvta.to.shared.u64 t, %1; cvt.u32.u64 %0, t; }"
        : "=r"(a) : "l"(p));
    return a;
}

__device__ __forceinline__ uint32_t b2u(__nv_bfloat162 v) {
    return *reinterpret_cast<uint32_t*>(&v);
}

__device__ __forceinline__ void ldsm_x4(uint32_t r[4], uint32_t addr) {
    asm volatile("ldmatrix.sync.aligned.m8n8.x4.shared.b16 {%0,%1,%2,%3}, [%4];"
                 : "=r"(r[0]), "=r"(r[1]), "=r"(r[2]), "=r"(r[3]) : "r"(addr));
}

__device__ __forceinline__ void mma16816(float c[4], const uint32_t a[4],
                                         uint32_t b0, uint32_t b1) {
    asm volatile(
        "mma.sync.aligned.m16n8k16.row.col.f32.bf16.bf16.f32 "
        "{%0,%1,%2,%3}, {%4,%5,%6,%7}, {%8,%9}, {%0,%1,%2,%3};"
        : "+f"(c[0]), "+f"(c[1]), "+f"(c[2]), "+f"(c[3])
        : "r"(a[0]), "r"(a[1]), "r"(a[2]), "r"(a[3]), "r"(b0), "r"(b1));
}

#define GBAR(id) asm volatile("bar.sync %0, 128;" :: "r"(id) : "memory")

// ---------------------------------------------------------------------------
__global__ void ces_prep(const float* __restrict__ wr, const float* __restrict__ wi) {
    int idx = blockIdx.x * blockDim.x + threadIdx.x;
    if (idx >= 16384) return;
    float a = wr[idx], b = wi[idx];
    float la = 0.5f * logf(fmaf(a, a, b * b));
    float an = atan2f(b, a);
    __nv_bfloat16 lah = __float2bfloat16(la);
    __nv_bfloat16 lal = __float2bfloat16(la - __bfloat162float(lah));
    __nv_bfloat16 anh = __float2bfloat16(an);
    __nv_bfloat16 anl = __float2bfloat16(an - __bfloat162float(anh));
    g_W[0 * 16384 + idx] = lah;
    g_W[1 * 16384 + idx] = lal;
    g_W[2 * 16384 + idx] = anh;
    g_W[3 * 16384 + idx] = anl;
}

// ---------------------------------------------------------------------------
// 8 warps = 2 groups x 4 warps. Group tile: 64 rows x 128 cols.
// Within group: wm = lwid&1 (32 rows), wn = lwid>>1 (64 cols).
// ---------------------------------------------------------------------------
__global__ void __launch_bounds__(256, 1)
ces_main(const float* __restrict__ x, const float* __restrict__ bias,
         float* __restrict__ out) {
    extern __shared__ char smem[];
    const uint32_t sb = smem_u32(smem);
    const int tid  = threadIdx.x;
    const int lane = tid & 31;
    const int wid  = tid >> 5;
    const int g    = wid >> 2;        // group 0/1
    const int lwid = wid & 3;         // warp in group
    const int wm   = lwid & 1;
    const int wn   = lwid >> 1;

    // ---- copy W into padded smem, once (all 256 threads) ----
    for (int r = tid; r < 512; r += 256) {
        const uint4* src = (const uint4*)(g_W + r * 128);
        uint4* dst = (uint4*)(smem + OFF_W + ((uint32_t)(r >> 7) * 17408u +
                                              (uint32_t)(r & 127) * LDS_STRIDE) * 2u);
        #pragma unroll
        for (int j = 0; j < 16; ++j) dst[j] = src[j];
    }
    if (tid < 128) ((float*)(smem + OFF_BIAS))[tid] = bias[tid];
    __syncthreads();

    // per-thread bias pairs (tile-invariant)
    float bs0[8], bs1[8];
    {
        const float* sbias = (const float*)(smem + OFF_BIAS);
        #pragma unroll
        for (int nt = 0; nt < 8; ++nt) {
            int c = wn * 64 + nt * 8 + 2 * (lane & 3);
            bs0[nt] = sbias[c];
            bs1[nt] = sbias[c + 1];
        }
    }

    // ---- anti-phase stagger: group 1 delays ~half a tile period ----
    if (g == 1) {
        long long t0 = clock64();
        while (clock64() - t0 < STAGGER_CYC) { }
    }

    // ldmatrix per-thread byte offsets
    const uint32_t aoff = ((uint32_t)(wm * 32 + (lane & 15)) * LDS_STRIDE +
                           (uint32_t)((lane >> 4) * 8)) * 2u;
    const uint32_t boff = ((uint32_t)(wn * 64 + ((lane & 7) | ((lane & 16) >> 1))) * LDS_STRIDE +
                           (uint32_t)(lane & 8)) * 2u;

    const uint32_t xbase   = sb + (uint32_t)g * 34816u;
    const uint32_t abase_h = xbase + aoff;
    const uint32_t abase_l = xbase + 17408u + aoff;
    const uint32_t MI_STEP = 16u * LDS_STRIDE * 2u;

    const int xrow0 = lwid;           // rows lwid + 4*j  (64 rows, 128 threads)
    const int xcol  = lane * 4;
    const int bar_id = g + 1;

    for (int tile = blockIdx.x * 2 + g; tile < N_TILES; tile += 2 * gridDim.x) {
        GBAR(bar_id);   // group's previous-tile ldsm done before X rewrite

        // ---- load x (coalesced), split hi/lo, STS ----
        #pragma unroll
        for (int jb = 0; jb < 2; ++jb) {
            float4 v[8];
            #pragma unroll
            for (int j = 0; j < 8; ++j) {
                size_t row = (size_t)tile * 64 + xrow0 + 4 * (jb * 8 + j);
                v[j] = __ldg((const float4*)(x + row * 128 + xcol));
            }
            #pragma unroll
            for (int j = 0; j < 8; ++j) {
                int row = xrow0 + 4 * (jb * 8 + j);
                __nv_bfloat162 h0 = __float22bfloat162_rn(make_float2(v[j].x, v[j].y));
                __nv_bfloat162 h1 = __float22bfloat162_rn(make_float2(v[j].z, v[j].w));
                __nv_bfloat162 L0 = __float22bfloat162_rn(make_float2(
                    v[j].x - __bfloat162float(h0.x), v[j].y - __bfloat162float(h0.y)));
                __nv_bfloat162 L1 = __float22bfloat162_rn(make_float2(
                    v[j].z - __bfloat162float(h1.x), v[j].w - __bfloat162float(h1.y)));
                uint32_t off = ((uint32_t)row * LDS_STRIDE + (uint32_t)xcol) * 2u;
                asm volatile("st.shared.v2.b32 [%0], {%1,%2};"
                             :: "r"(xbase + off), "r"(b2u(h0)), "r"(b2u(h1)) : "memory");
                asm volatile("st.shared.v2.b32 [%0], {%1,%2};"
                             :: "r"(xbase + 17408u + off), "r"(b2u(L0)), "r"(b2u(L1)) : "memory");
            }
        }
        GBAR(bar_id);

        // ---- accumulators: log = 0, ang = bias (folded) ----
        float acc[2][2][8][4];
        #pragma unroll
        for (int i = 0; i < 2; ++i)
            #pragma unroll
            for (int n = 0; n < 8; ++n) {
                #pragma unroll
                for (int q = 0; q < 4; ++q) acc[0][i][n][q] = 0.f;
                acc[1][i][n][0] = bs0[n];
                acc[1][i][n][1] = bs1[n];
                acc[1][i][n][2] = bs0[n];
                acc[1][i][n][3] = bs1[n];
            }

        // ---- fused k-loop: every fragment loaded once per k-step ----
        uint32_t ah[2][2][4], al[2][2][4];   // [buf][mi][4]
        ldsm_x4(ah[0][0], abase_h);
        ldsm_x4(ah[0][1], abase_h + MI_STEP);
        ldsm_x4(al[0][0], abase_l);
        ldsm_x4(al[0][1], abase_l + MI_STEP);

        #pragma unroll
        for (int k = 0; k < 8; ++k) {
            const int cur = k & 1, nxt = cur ^ 1;
            const uint32_t kb = (uint32_t)k * 32u;

            if (k < 7) {
                const uint32_t kn = kb + 32u;
                ldsm_x4(ah[nxt][0], abase_h + kn);
                ldsm_x4(ah[nxt][1], abase_h + MI_STEP + kn);
                ldsm_x4(al[nxt][0], abase_l + kn);
                ldsm_x4(al[nxt][1], abase_l + MI_STEP + kn);
            }

            // ---- group 1: hi-weights (logH, angH), xh then xl ----
            {
                uint32_t b[2][4][4];
                #pragma unroll
                for (int s = 0; s < 2; ++s) {
                    const uint32_t wb = sb + OFF_W + (uint32_t)(s * 2) * 34816u + boff + kb;
                    #pragma unroll
                    for (int np = 0; np < 4; ++np)
                        ldsm_x4(b[s][np], wb + (uint32_t)np * MI_STEP);
                }
                #pragma unroll
                for (int s = 0; s < 2; ++s)
                    #pragma unroll
                    for (int np = 0; np < 4; ++np) {
                        mma16816(acc[s][0][np * 2],     ah[cur][0], b[s][np][0], b[s][np][1]);
                        mma16816(acc[s][1][np * 2],     ah[cur][1], b[s][np][0], b[s][np][1]);
                        mma16816(acc[s][0][np * 2 + 1], ah[cur][0], b[s][np][2], b[s][np][3]);
                        mma16816(acc[s][1][np * 2 + 1], ah[cur][1], b[s][np][2], b[s][np][3]);
                    }
                #pragma unroll
                for (int s = 0; s < 2; ++s)
                    #pragma unroll
                    for (int np = 0; np < 4; ++np) {
                        mma16816(acc[s][0][np * 2],     al[cur][0], b[s][np][0], b[s][np][1]);
                        mma16816(acc[s][1][np * 2],     al[cur][1], b[s][np][0], b[s][np][1]);
                        mma16816(acc[s][0][np * 2 + 1], al[cur][0], b[s][np][2], b[s][np][3]);
                        mma16816(acc[s][1][np * 2 + 1], al[cur][1], b[s][np][2], b[s][np][3]);
                    }
            }

            // ---- group 2: lo-weights (logL, angL), xh only ----
            {
                uint32_t b[2][4][4];
                #pragma unroll
                for (int s = 0; s < 2; ++s) {
                    const uint32_t wb = sb + OFF_W + (uint32_t)(s * 2 + 1) * 34816u + boff + kb;
                    #pragma unroll
                    for (int np = 0; np < 4; ++np)
                        ldsm_x4(b[s][np], wb + (uint32_t)np * MI_STEP);
                }
                #pragma unroll
                for (int s = 0; s < 2; ++s)
                    #pragma unroll
                    for (int np = 0; np < 4; ++np) {
                        mma16816(acc[s][0][np * 2],     ah[cur][0], b[s][np][0], b[s][np][1]);
                        mma16816(acc[s][1][np * 2],     ah[cur][1], b[s][np][0], b[s][np][1]);
                        mma16816(acc[s][0][np * 2 + 1], ah[cur][0], b[s][np][2], b[s][np][3]);
                        mma16816(acc[s][1][np * 2 + 1], ah[cur][1], b[s][np][2], b[s][np][3]);
                    }
            }
        }

        // ---- epilogue: out = cos(ang) * exp(log)   (bias already in ang) ----
        #pragma unroll
        for (int mt = 0; mt < 2; ++mt) {
            size_t r0 = (size_t)tile * 64 + wm * 32 + mt * 16 + (lane >> 2);
            float* p0 = out + r0 * 128 + wn * 64 + 2 * (lane & 3);
            #pragma unroll
            for (int nt = 0; nt < 8; ++nt) {
                const float* al_ = acc[1][mt][nt];
                const float* lg  = acc[0][mt][nt];
                float2 o0, o1;
                o0.x = __cosf(al_[0]) * __expf(lg[0]);
                o0.y = __cosf(al_[1]) * __expf(lg[1]);
                o1.x = __cosf(al_[2]) * __expf(lg[2]);
                o1.y = __cosf(al_[3]) * __expf(lg[3]);
                *(float2*)(p0 + nt * 8) = o0;
                *(float2*)(p0 + nt * 8 + 8 * 128) = o1;
            }
        }
    }
}

// ---------------------------------------------------------------------------
extern "C" void kernel_launch(void* const* d_in, const int* in_sizes, int n_in,
                              void* d_out, int out_size) {
    const float* x    = (const float*)d_in[0];
    const float* wr   = (const float*)d_in[1];
    const float* wi   = (const float*)d_in[2];
    const float* bias = (const float*)d_in[3];
    float* out = (float*)d_out;
    (void)in_sizes; (void)n_in; (void)out_size;

    cudaFuncSetAttribute(ces_main, cudaFuncAttributeMaxDynamicSharedMemorySize,
                         (int)SMEM_BYTES);

    ces_prep<<<64, 256>>>(wr, wi);
    ces_main<<<GRID_CTAS, 256, SMEM_BYTES>>>(x, bias, out);
}

// round 7
// speedup vs baseline: 1.4472x; 1.4470x over previous
#include <cuda_runtime.h>
#include <cuda_fp16.h>
#include <cstdint>

// ============================================================================
// CESLayer: out[b,o] = cos( x@angle^T + bias ) * exp( x@log|w|^T )
// B=262144, I=O=128.  mma.sync **fp16** (exact products in fp32 accum):
//   angle = xh*angH + xl*angH + xh*angL   (3 passes, err ~1e-6)
//   logmag = xh*logH                      (1 pass,  err ~2e-4 — budget ok)
// R7: R4 structure (154us) with 4 passes instead of 6 (-33% tensor work).
// ============================================================================

#define N_TILES   4096            // 64-row tiles
#define GRID_CTAS 148
#define LDS_STRIDE 136            // fp16 elems per smem row (128+8 pad)

// smem byte offsets
// group g X: [g*34816, +17408) xh, +17408 xl   (64 rows x 136 x fp16)
#define OFF_W    69632u           // 3 mats * 34816: [angH, angL, logH]
#define OFF_BIAS 174080u
#define SMEM_BYTES 174592u

__device__ __align__(16) __half g_W[3 * 16384];

// ---------------------------------------------------------------------------
__device__ __forceinline__ uint32_t smem_u32(const void* p) {
    uint32_t a;
    asm("{ .reg .u64 t; cvta.to.shared.u64 t, %1; cvt.u32.u64 %0, t; }"
        : "=r"(a) : "l"(p));
    return a;
}

__device__ __forceinline__ uint32_t h2u(__half2 v) {
    return *reinterpret_cast<uint32_t*>(&v);
}

__device__ __forceinline__ void ldsm_x4(uint32_t r[4], uint32_t addr) {
    asm volatile("ldmatrix.sync.aligned.m8n8.x4.shared.b16 {%0,%1,%2,%3}, [%4];"
                 : "=r"(r[0]), "=r"(r[1]), "=r"(r[2]), "=r"(r[3]) : "r"(addr));
}

__device__ __forceinline__ void mma16816(float c[4], const uint32_t a[4],
                                         uint32_t b0, uint32_t b1) {
    asm volatile(
        "mma.sync.aligned.m16n8k16.row.col.f32.f16.f16.f32 "
        "{%0,%1,%2,%3}, {%4,%5,%6,%7}, {%8,%9}, {%0,%1,%2,%3};"
        : "+f"(c[0]), "+f"(c[1]), "+f"(c[2]), "+f"(c[3])
        : "r"(a[0]), "r"(a[1]), "r"(a[2]), "r"(a[3]), "r"(b0), "r"(b1));
}

#define GBAR(id) asm volatile("bar.sync %0, 128;" :: "r"(id) : "memory")

// ---------------------------------------------------------------------------
// Prep: w -> angle (fp16 hi/lo) and log|w| (fp16 single).
// ---------------------------------------------------------------------------
__global__ void ces_prep(const float* __restrict__ wr, const float* __restrict__ wi) {
    int idx = blockIdx.x * blockDim.x + threadIdx.x;
    if (idx >= 16384) return;
    float a = wr[idx], b = wi[idx];
    float la = 0.5f * logf(fmaf(a, a, b * b));
    float an = atan2f(b, a);
    __half anh = __float2half_rn(an);
    __half anl = __float2half_rn(an - __half2float(anh));
    __half lah = __float2half_rn(la);
    g_W[0 * 16384 + idx] = anh;   // angH
    g_W[1 * 16384 + idx] = anl;   // angL
    g_W[2 * 16384 + idx] = lah;   // logH
}

// ---------------------------------------------------------------------------
// 8 warps = 2 groups x 4 warps. Group tile: 64 rows x 128 cols.
// Within group: wm = lwid&1 (32 rows), wn = lwid>>1 (64 cols).
// ---------------------------------------------------------------------------
__global__ void __launch_bounds__(256, 1)
ces_main(const float* __restrict__ x, const float* __restrict__ bias,
         float* __restrict__ out) {
    extern __shared__ char smem[];
    const uint32_t sb = smem_u32(smem);
    const int tid  = threadIdx.x;
    const int lane = tid & 31;
    const int wid  = tid >> 5;
    const int g    = wid >> 2;        // group 0/1
    const int lwid = wid & 3;         // warp in group
    const int wm   = lwid & 1;
    const int wn   = lwid >> 1;

    // ---- copy W (3 x 128 x 128 fp16) into padded smem, once ----
    for (int r = tid; r < 384; r += 256) {
        const uint4* src = (const uint4*)(g_W + r * 128);
        uint4* dst = (uint4*)(smem + OFF_W + ((uint32_t)(r >> 7) * 17408u +
                                              (uint32_t)(r & 127) * LDS_STRIDE) * 2u);
        #pragma unroll
        for (int j = 0; j < 16; ++j) dst[j] = src[j];
    }
    if (tid < 128) ((float*)(smem + OFF_BIAS))[tid] = bias[tid];
    __syncthreads();

    // per-thread bias pairs (tile-invariant)
    float bs0[8], bs1[8];
    {
        const float* sbias = (const float*)(smem + OFF_BIAS);
        #pragma unroll
        for (int nt = 0; nt < 8; ++nt) {
            int c = wn * 64 + nt * 8 + 2 * (lane & 3);
            bs0[nt] = sbias[c];
            bs1[nt] = sbias[c + 1];
        }
    }

    // ldmatrix per-thread byte offsets
    const uint32_t aoff = ((uint32_t)(wm * 32 + (lane & 15)) * LDS_STRIDE +
                           (uint32_t)((lane >> 4) * 8)) * 2u;
    const uint32_t boff = ((uint32_t)(wn * 64 + ((lane & 7) | ((lane & 16) >> 1))) * LDS_STRIDE +
                           (uint32_t)(lane & 8)) * 2u;

    const uint32_t xbase   = sb + (uint32_t)g * 34816u;
    const uint32_t abase_h = xbase + aoff;
    const uint32_t abase_l = xbase + 17408u + aoff;
    const uint32_t MI_STEP = 16u * LDS_STRIDE * 2u;

    const int xrow0 = lwid;           // rows lwid + 4*j  (64 rows, 128 threads)
    const int xcol  = lane * 4;
    const int bar_id = g + 1;

    for (int tile = blockIdx.x * 2 + g; tile < N_TILES; tile += 2 * gridDim.x) {
        GBAR(bar_id);   // group's previous-tile ldsm done before X rewrite

        // ---- load x (coalesced), split fp16 hi/lo, STS ----
        #pragma unroll
        for (int jb = 0; jb < 2; ++jb) {
            float4 v[8];
            #pragma unroll
            for (int j = 0; j < 8; ++j) {
                size_t row = (size_t)tile * 64 + xrow0 + 4 * (jb * 8 + j);
                v[j] = __ldg((const float4*)(x + row * 128 + xcol));
            }
            #pragma unroll
            for (int j = 0; j < 8; ++j) {
                int row = xrow0 + 4 * (jb * 8 + j);
                __half2 h0 = __floats2half2_rn(v[j].x, v[j].y);
                __half2 h1 = __floats2half2_rn(v[j].z, v[j].w);
                __half2 L0 = __floats2half2_rn(v[j].x - __low2float(h0),
                                               v[j].y - __high2float(h0));
                __half2 L1 = __floats2half2_rn(v[j].z - __low2float(h1),
                                               v[j].w - __high2float(h1));
                uint32_t off = ((uint32_t)row * LDS_STRIDE + (uint32_t)xcol) * 2u;
                asm volatile("st.shared.v2.b32 [%0], {%1,%2};"
                             :: "r"(xbase + off), "r"(h2u(h0)), "r"(h2u(h1)) : "memory");
                asm volatile("st.shared.v2.b32 [%0], {%1,%2};"
                             :: "r"(xbase + 17408u + off), "r"(h2u(L0)), "r"(h2u(L1)) : "memory");
            }
        }
        GBAR(bar_id);

        // ---- accumulators: [mat(log/ang)][mtile][ntile][4] ----
        float acc[2][2][8][4];
        #pragma unroll
        for (int m = 0; m < 2; ++m)
            #pragma unroll
            for (int i = 0; i < 2; ++i)
                #pragma unroll
                for (int n = 0; n < 8; ++n)
                    #pragma unroll
                    for (int q = 0; q < 4; ++q) acc[m][i][n][q] = 0.f;

        // ---- fused k-loop: 4 passes (angH*xh, logH*xh, angH*xl, angL*xh) ----
        uint32_t ah[2][2][4], al[2][2][4];   // [buf][mi][4]
        ldsm_x4(ah[0][0], abase_h);
        ldsm_x4(ah[0][1], abase_h + MI_STEP);
        ldsm_x4(al[0][0], abase_l);
        ldsm_x4(al[0][1], abase_l + MI_STEP);

        #pragma unroll
        for (int k = 0; k < 8; ++k) {
            const int cur = k & 1, nxt = cur ^ 1;
            const uint32_t kb = (uint32_t)k * 32u;

            if (k < 7) {
                const uint32_t kn = kb + 32u;
                ldsm_x4(ah[nxt][0], abase_h + kn);
                ldsm_x4(ah[nxt][1], abase_h + MI_STEP + kn);
                ldsm_x4(al[nxt][0], abase_l + kn);
                ldsm_x4(al[nxt][1], abase_l + MI_STEP + kn);
            }

            // B fragments: angH, angL, logH (4 ldsm.x4 each)
            uint32_t bAH[4][4], bAL[4][4], bLH[4][4];
            {
                const uint32_t wb = sb + OFF_W + boff + kb;
                #pragma unroll
                for (int np = 0; np < 4; ++np) ldsm_x4(bAH[np], wb + (uint32_t)np * MI_STEP);
                #pragma unroll
                for (int np = 0; np < 4; ++np) ldsm_x4(bAL[np], wb + 34816u + (uint32_t)np * MI_STEP);
                #pragma unroll
                for (int np = 0; np < 4; ++np) ldsm_x4(bLH[np], wb + 69632u + (uint32_t)np * MI_STEP);
            }

            // pass 1: ang += xh * angH
            #pragma unroll
            for (int np = 0; np < 4; ++np) {
                mma16816(acc[1][0][np * 2],     ah[cur][0], bAH[np][0], bAH[np][1]);
                mma16816(acc[1][1][np * 2],     ah[cur][1], bAH[np][0], bAH[np][1]);
                mma16816(acc[1][0][np * 2 + 1], ah[cur][0], bAH[np][2], bAH[np][3]);
                mma16816(acc[1][1][np * 2 + 1], ah[cur][1], bAH[np][2], bAH[np][3]);
            }
            // pass 2: log += xh * logH  (spaces acc[1] RAW pairs)
            #pragma unroll
            for (int np = 0; np < 4; ++np) {
                mma16816(acc[0][0][np * 2],     ah[cur][0], bLH[np][0], bLH[np][1]);
                mma16816(acc[0][1][np * 2],     ah[cur][1], bLH[np][0], bLH[np][1]);
                mma16816(acc[0][0][np * 2 + 1], ah[cur][0], bLH[np][2], bLH[np][3]);
                mma16816(acc[0][1][np * 2 + 1], ah[cur][1], bLH[np][2], bLH[np][3]);
            }
            // pass 3: ang += xl * angH
            #pragma unroll
            for (int np = 0; np < 4; ++np) {
                mma16816(acc[1][0][np * 2],     al[cur][0], bAH[np][0], bAH[np][1]);
                mma16816(acc[1][1][np * 2],     al[cur][1], bAH[np][0], bAH[np][1]);
                mma16816(acc[1][0][np * 2 + 1], al[cur][0], bAH[np][2], bAH[np][3]);
                mma16816(acc[1][1][np * 2 + 1], al[cur][1], bAH[np][2], bAH[np][3]);
            }
            // pass 4: ang += xh * angL
            #pragma unroll
            for (int np = 0; np < 4; ++np) {
                mma16816(acc[1][0][np * 2],     ah[cur][0], bAL[np][0], bAL[np][1]);
                mma16816(acc[1][1][np * 2],     ah[cur][1], bAL[np][0], bAL[np][1]);
                mma16816(acc[1][0][np * 2 + 1], ah[cur][0], bAL[np][2], bAL[np][3]);
                mma16816(acc[1][1][np * 2 + 1], ah[cur][1], bAL[np][2], bAL[np][3]);
            }
        }

        // ---- epilogue: out = cos(ang + bias) * exp(log) ----
        #pragma unroll
        for (int mt = 0; mt < 2; ++mt) {
            size_t r0 = (size_t)tile * 64 + wm * 32 + mt * 16 + (lane >> 2);
            float* p0 = out + r0 * 128 + wn * 64 + 2 * (lane & 3);
            #pragma unroll
            for (int nt = 0; nt < 8; ++nt) {
                const float* al_ = acc[1][mt][nt];
                const float* lg  = acc[0][mt][nt];
                float2 o0, o1;
                o0.x = __cosf(al_[0] + bs0[nt]) * __expf(lg[0]);
                o0.y = __cosf(al_[1] + bs1[nt]) * __expf(lg[1]);
                o1.x = __cosf(al_[2] + bs0[nt]) * __expf(lg[2]);
                o1.y = __cosf(al_[3] + bs1[nt]) * __expf(lg[3]);
                *(float2*)(p0 + nt * 8) = o0;
                *(float2*)(p0 + nt * 8 + 8 * 128) = o1;
            }
        }
    }
}

// ---------------------------------------------------------------------------
extern "C" void kernel_launch(void* const* d_in, const int* in_sizes, int n_in,
                              void* d_out, int out_size) {
    const float* x    = (const float*)d_in[0];
    const float* wr   = (const float*)d_in[1];
    const float* wi   = (const float*)d_in[2];
    const float* bias = (const float*)d_in[3];
    float* out = (float*)d_out;
    (void)in_sizes; (void)n_in; (void)out_size;

    cudaFuncSetAttribute(ces_main, cudaFuncAttributeMaxDynamicSharedMemorySize,
                         (int)SMEM_BYTES);

    ces_prep<<<64, 256>>>(wr, wi);
    ces_main<<<GRID_CTAS, 256, SMEM_BYTES>>>(x, bias, out);
}

// round 8
// speedup vs baseline: 1.5134x; 1.0457x over previous
#include <cuda_runtime.h>
#include <cuda_fp16.h>
#include <cstdint>

// ============================================================================
// CESLayer: out[b,o] = cos( x@angle^T + bias ) * exp( x@log|w|^T )
// B=262144, I=O=128.  fp16 mma.sync (exact products):
//   angle = xh*angH + xl*angH + xh*angL ; logmag = xh*logH   (4 passes)
// R8: cp.async f32 X staging (latency under epilogue) + in-k-loop A-fragment
//     conversion via LDS.64 f32 (no split phase, no A-ldsm, no STS).
// ============================================================================

#define N_TILES   4096            // 64-row tiles
#define GRID_CTAS 148
#define LDS_STRIDE 136            // elems/row: f32 for X, fp16 for W

// smem byte offsets
// X: group g at OFF_X + g*34816  (64 rows x 136 f32 = 34816 B)
#define OFF_X    0u
#define OFF_W    69632u           // 3 mats * 34816: [angH, angL, logH] fp16
#define OFF_BIAS 174080u
#define SMEM_BYTES 174592u

__device__ __align__(16) __half g_W[3 * 16384];

// ---------------------------------------------------------------------------
__device__ __forceinline__ uint32_t smem_u32(const void* p) {
    uint32_t a;
    asm("{ .reg .u64 t; cvta.to.shared.u64 t, %1; cvt.u32.u64 %0, t; }"
        : "=r"(a) : "l"(p));
    return a;
}

__device__ __forceinline__ uint32_t h2u(__half2 v) {
    return *reinterpret_cast<uint32_t*>(&v);
}

__device__ __forceinline__ void ldsm_x4(uint32_t r[4], uint32_t addr) {
    asm volatile("ldmatrix.sync.aligned.m8n8.x4.shared.b16 {%0,%1,%2,%3}, [%4];"
                 : "=r"(r[0]), "=r"(r[1]), "=r"(r[2]), "=r"(r[3]) : "r"(addr));
}

__device__ __forceinline__ void lds64(float2& p, uint32_t addr) {
    asm volatile("ld.shared.v2.f32 {%0,%1}, [%2];"
                 : "=f"(p.x), "=f"(p.y) : "r"(addr));
}

__device__ __forceinline__ void mma16816(float c[4], const uint32_t a[4],
                                         uint32_t b0, uint32_t b1) {
    asm volatile(
        "mma.sync.aligned.m16n8k16.row.col.f32.f16.f16.f32 "
        "{%0,%1,%2,%3}, {%4,%5,%6,%7}, {%8,%9}, {%0,%1,%2,%3};"
        : "+f"(c[0]), "+f"(c[1]), "+f"(c[2]), "+f"(c[3])
        : "r"(a[0]), "r"(a[1]), "r"(a[2]), "r"(a[3]), "r"(b0), "r"(b1));
}

// split one f32 pair into fp16 hi + lo packed halves
__device__ __forceinline__ void cvt_hl(float2 p, uint32_t& h, uint32_t& l) {
    __half2 hh = __floats2half2_rn(p.x, p.y);
    __half2 ll = __floats2half2_rn(p.x - __low2float(hh), p.y - __high2float(hh));
    h = h2u(hh);
    l = h2u(ll);
}

#define GBAR(id) asm volatile("bar.sync %0, 128;" :: "r"(id) : "memory")
#define CP_ASYNC16(dst, src) \
    asm volatile("cp.async.cg.shared.global [%0], [%1], 16;" :: "r"(dst), "l"(src))
#define CP_COMMIT() asm volatile("cp.async.commit_group;" ::: "memory")
#define CP_WAIT0()  asm volatile("cp.async.wait_group 0;" ::: "memory")

// ---------------------------------------------------------------------------
// Prep: w -> angle (fp16 hi/lo) and log|w| (fp16).
// ---------------------------------------------------------------------------
__global__ void ces_prep(const float* __restrict__ wr, const float* __restrict__ wi) {
    int idx = blockIdx.x * blockDim.x + threadIdx.x;
    if (idx >= 16384) return;
    float a = wr[idx], b = wi[idx];
    float la = 0.5f * logf(fmaf(a, a, b * b));
    float an = atan2f(b, a);
    __half anh = __float2half_rn(an);
    __half anl = __float2half_rn(an - __half2float(anh));
    g_W[0 * 16384 + idx] = anh;   // angH
    g_W[1 * 16384 + idx] = anl;   // angL
    g_W[2 * 16384 + idx] = __float2half_rn(la);  // logH
}

// ---------------------------------------------------------------------------
// 8 warps = 2 groups x 4 warps. Group tile: 64 rows x 128 cols.
// Within group: wm = lwid&1 (32 rows), wn = lwid>>1 (64 cols).
// ---------------------------------------------------------------------------
__global__ void __launch_bounds__(256, 1)
ces_main(const float* __restrict__ x, const float* __restrict__ bias,
         float* __restrict__ out) {
    extern __shared__ char smem[];
    const uint32_t sb = smem_u32(smem);
    const int tid    = threadIdx.x;
    const int lane   = tid & 31;
    const int wid    = tid >> 5;
    const int g      = wid >> 2;      // group 0/1
    const int lwid   = wid & 3;       // warp in group
    const int wm     = lwid & 1;
    const int wn     = lwid >> 1;
    const int wg_tid = tid & 127;

    const uint32_t xbase = sb + OFF_X + (uint32_t)g * 34816u;

    // cp.async mapping: per j, row = j*4 + wg_tid>>5, 16B chunk = (wg_tid&31)
    const uint32_t cp_dst0 = xbase + (uint32_t)(wg_tid >> 5) * 544u +
                             (uint32_t)(lane) * 16u;
    const int cp_row0 = (wg_tid >> 5);
    const int cp_col  = lane * 4;

    // ---- prologue: stage first tile's x, copy W, bias ----
    int tile = blockIdx.x * 2 + g;
    if (tile < N_TILES) {
        const float* src = x + (size_t)tile * 64 * 128;
        #pragma unroll
        for (int j = 0; j < 16; ++j)
            CP_ASYNC16(cp_dst0 + (uint32_t)j * 2176u,
                       src + (size_t)(cp_row0 + j * 4) * 128 + cp_col);
        CP_COMMIT();
    }

    for (int r = tid; r < 384; r += 256) {
        const uint4* srcw = (const uint4*)(g_W + r * 128);
        uint4* dst = (uint4*)(smem + OFF_W + ((uint32_t)(r >> 7) * 17408u +
                                              (uint32_t)(r & 127) * LDS_STRIDE) * 2u);
        #pragma unroll
        for (int j = 0; j < 16; ++j) dst[j] = srcw[j];
    }
    if (tid < 128) ((float*)(smem + OFF_BIAS))[tid] = bias[tid];
    CP_WAIT0();
    __syncthreads();

    // per-thread bias pairs (tile-invariant)
    float bs0[8], bs1[8];
    {
        const float* sbias = (const float*)(smem + OFF_BIAS);
        #pragma unroll
        for (int nt = 0; nt < 8; ++nt) {
            int c = wn * 64 + nt * 8 + 2 * (lane & 3);
            bs0[nt] = sbias[c];
            bs1[nt] = sbias[c + 1];
        }
    }

    // A-side LDS base (f32): row = wm*32 + (lane>>2), col = (lane&3)*2
    const uint32_t a_lds = xbase +
        ((uint32_t)(wm * 32 + (lane >> 2)) * LDS_STRIDE + (uint32_t)((lane & 3) * 2)) * 4u;
    const uint32_t MI_X  = 16u * LDS_STRIDE * 4u;   // +16 rows (f32)
    const uint32_t R8_X  = 8u * LDS_STRIDE * 4u;    // +8 rows

    // B-side ldmatrix offset (fp16)
    const uint32_t boff = ((uint32_t)(wn * 64 + ((lane & 7) | ((lane & 16) >> 1))) * LDS_STRIDE +
                           (uint32_t)(lane & 8)) * 2u;
    const uint32_t MI_W = 16u * LDS_STRIDE * 2u;

    const int bar_id = g + 1;

    for (; tile < N_TILES; tile += 2 * GRID_CTAS) {
        // ---- accumulators: [mat(log/ang)][mtile][ntile][4] ----
        float acc[2][2][8][4];
        #pragma unroll
        for (int m = 0; m < 2; ++m)
            #pragma unroll
            for (int i = 0; i < 2; ++i)
                #pragma unroll
                for (int n = 0; n < 8; ++n)
                    #pragma unroll
                    for (int q = 0; q < 4; ++q) acc[m][i][n][q] = 0.f;

        // ---- fused k-loop ----
        #pragma unroll
        for (int k = 0; k < 8; ++k) {
            // A fragments: LDS f32 pairs -> fp16 hi/lo in registers
            uint32_t ah[2][4], al[2][4];
            #pragma unroll
            for (int mi = 0; mi < 2; ++mi) {
                const uint32_t ab = a_lds + (uint32_t)mi * MI_X + (uint32_t)k * 64u;
                float2 p0, p1, p2, p3;
                lds64(p0, ab);
                lds64(p1, ab + R8_X);
                lds64(p2, ab + 32u);
                lds64(p3, ab + R8_X + 32u);
                cvt_hl(p0, ah[mi][0], al[mi][0]);
                cvt_hl(p1, ah[mi][1], al[mi][1]);
                cvt_hl(p2, ah[mi][2], al[mi][2]);
                cvt_hl(p3, ah[mi][3], al[mi][3]);
            }

            // B fragments: angH, angL, logH
            uint32_t bAH[4][4], bAL[4][4], bLH[4][4];
            {
                const uint32_t wb = sb + OFF_W + boff + (uint32_t)k * 32u;
                #pragma unroll
                for (int np = 0; np < 4; ++np) ldsm_x4(bAH[np], wb + (uint32_t)np * MI_W);
                #pragma unroll
                for (int np = 0; np < 4; ++np) ldsm_x4(bAL[np], wb + 34816u + (uint32_t)np * MI_W);
                #pragma unroll
                for (int np = 0; np < 4; ++np) ldsm_x4(bLH[np], wb + 69632u + (uint32_t)np * MI_W);
            }

            // pass 1: ang += xh * angH
            #pragma unroll
            for (int np = 0; np < 4; ++np) {
                mma16816(acc[1][0][np * 2],     ah[0], bAH[np][0], bAH[np][1]);
                mma16816(acc[1][1][np * 2],     ah[1], bAH[np][0], bAH[np][1]);
                mma16816(acc[1][0][np * 2 + 1], ah[0], bAH[np][2], bAH[np][3]);
                mma16816(acc[1][1][np * 2 + 1], ah[1], bAH[np][2], bAH[np][3]);
            }
            // pass 2: log += xh * logH
            #pragma unroll
            for (int np = 0; np < 4; ++np) {
                mma16816(acc[0][0][np * 2],     ah[0], bLH[np][0], bLH[np][1]);
                mma16816(acc[0][1][np * 2],     ah[1], bLH[np][0], bLH[np][1]);
                mma16816(acc[0][0][np * 2 + 1], ah[0], bLH[np][2], bLH[np][3]);
                mma16816(acc[0][1][np * 2 + 1], ah[1], bLH[np][2], bLH[np][3]);
            }
            // pass 3: ang += xl * angH
            #pragma unroll
            for (int np = 0; np < 4; ++np) {
                mma16816(acc[1][0][np * 2],     al[0], bAH[np][0], bAH[np][1]);
                mma16816(acc[1][1][np * 2],     al[1], bAH[np][0], bAH[np][1]);
                mma16816(acc[1][0][np * 2 + 1], al[0], bAH[np][2], bAH[np][3]);
                mma16816(acc[1][1][np * 2 + 1], al[1], bAH[np][2], bAH[np][3]);
            }
            // pass 4: ang += xh * angL
            #pragma unroll
            for (int np = 0; np < 4; ++np) {
                mma16816(acc[1][0][np * 2],     ah[0], bAL[np][0], bAL[np][1]);
                mma16816(acc[1][1][np * 2],     ah[1], bAL[np][0], bAL[np][1]);
                mma16816(acc[1][0][np * 2 + 1], ah[0], bAL[np][2], bAL[np][3]);
                mma16816(acc[1][1][np * 2 + 1], ah[1], bAL[np][2], bAL[np][3]);
            }
        }

        GBAR(bar_id);   // all group warps done reading X[g]

        // ---- stage next tile's x (latency hidden under epilogue) ----
        {
            int nxt = tile + 2 * GRID_CTAS;
            if (nxt < N_TILES) {
                const float* src = x + (size_t)nxt * 64 * 128;
                #pragma unroll
                for (int j = 0; j < 16; ++j)
                    CP_ASYNC16(cp_dst0 + (uint32_t)j * 2176u,
                               src + (size_t)(cp_row0 + j * 4) * 128 + cp_col);
                CP_COMMIT();
            }
        }

        // ---- epilogue: out = cos(ang + bias) * exp(log) ----
        #pragma unroll
        for (int mt = 0; mt < 2; ++mt) {
            size_t r0 = (size_t)tile * 64 + wm * 32 + mt * 16 + (lane >> 2);
            float* p0 = out + r0 * 128 + wn * 64 + 2 * (lane & 3);
            #pragma unroll
            for (int nt = 0; nt < 8; ++nt) {
                const float* al_ = acc[1][mt][nt];
                const float* lg  = acc[0][mt][nt];
                float2 o0, o1;
                o0.x = __cosf(al_[0] + bs0[nt]) * __expf(lg[0]);
                o0.y = __cosf(al_[1] + bs1[nt]) * __expf(lg[1]);
                o1.x = __cosf(al_[2] + bs0[nt]) * __expf(lg[2]);
                o1.y = __cosf(al_[3] + bs1[nt]) * __expf(lg[3]);
                *(float2*)(p0 + nt * 8) = o0;
                *(float2*)(p0 + nt * 8 + 8 * 128) = o1;
            }
        }

        CP_WAIT0();
        GBAR(bar_id);   // X[g] refilled for the whole group
    }
}

// ---------------------------------------------------------------------------
extern "C" void kernel_launch(void* const* d_in, const int* in_sizes, int n_in,
                              void* d_out, int out_size) {
    const float* x    = (const float*)d_in[0];
    const float* wr   = (const float*)d_in[1];
    const float* wi   = (const float*)d_in[2];
    const float* bias = (const float*)d_in[3];
    float* out = (float*)d_out;
    (void)in_sizes; (void)n_in; (void)out_size;

    cudaFuncSetAttribute(ces_main, cudaFuncAttributeMaxDynamicSharedMemorySize,
                         (int)SMEM_BYTES);

    ces_prep<<<64, 256>>>(wr, wi);
    ces_main<<<GRID_CTAS, 256, SMEM_BYTES>>>(x, bias, out);
}

// round 10
// speedup vs baseline: 1.5948x; 1.0538x over previous
#include <cuda_runtime.h>
#include <cuda_fp16.h>
#include <cstdint>

// ============================================================================
// CESLayer: out[b,o] = cos( x@angle^T + bias ) * exp( x@log|w|^T )
// B=262144, I=O=128.  fp16 mma.sync (exact products):
//   angle = xh*angH + xl*angH + xh*angL ; logmag = xh*logH   (4 passes)
// R10: R9 with the cp.async chunk mapping FIXED (2048 chunks, j<8,
//      row=chunk>>5, col-chunk=chunk&31).  16 warps = 4 groups, 32x32 tiles.
// ============================================================================

#define N_TILES   4096            // 64-row tiles
#define GRID_CTAS 148
#define LDS_STRIDE 136            // elems/row: f32 for X, fp16 for W

// smem byte offsets
// X: row-block rb at rb*34816  (64 rows x 136 f32)
#define OFF_W    69632u           // 3 mats * 34816: [angH, angL, logH] fp16
#define OFF_BIAS 174080u
#define SMEM_BYTES 174592u

__device__ __align__(16) __half g_W[3 * 16384];

// ---------------------------------------------------------------------------
__device__ __forceinline__ uint32_t smem_u32(const void* p) {
    uint32_t a;
    asm("{ .reg .u64 t; cvta.to.shared.u64 t, %1; cvt.u32.u64 %0, t; }"
        : "=r"(a) : "l"(p));
    return a;
}

__device__ __forceinline__ uint32_t h2u(__half2 v) {
    return *reinterpret_cast<uint32_t*>(&v);
}

__device__ __forceinline__ void ldsm_x4(uint32_t r[4], uint32_t addr) {
    asm volatile("ldmatrix.sync.aligned.m8n8.x4.shared.b16 {%0,%1,%2,%3}, [%4];"
                 : "=r"(r[0]), "=r"(r[1]), "=r"(r[2]), "=r"(r[3]) : "r"(addr));
}

__device__ __forceinline__ void lds64(float2& p, uint32_t addr) {
    asm volatile("ld.shared.v2.f32 {%0,%1}, [%2];"
                 : "=f"(p.x), "=f"(p.y) : "r"(addr));
}

__device__ __forceinline__ void mma16816(float c[4], const uint32_t a[4],
                                         uint32_t b0, uint32_t b1) {
    asm volatile(
        "mma.sync.aligned.m16n8k16.row.col.f32.f16.f16.f32 "
        "{%0,%1,%2,%3}, {%4,%5,%6,%7}, {%8,%9}, {%0,%1,%2,%3};"
        : "+f"(c[0]), "+f"(c[1]), "+f"(c[2]), "+f"(c[3])
        : "r"(a[0]), "r"(a[1]), "r"(a[2]), "r"(a[3]), "r"(b0), "r"(b1));
}

// split one f32 pair into fp16 hi + lo packed halves
__device__ __forceinline__ void cvt_hl(float2 p, uint32_t& h, uint32_t& l) {
    __half2 hh = __floats2half2_rn(p.x, p.y);
    __half2 ll = __floats2half2_rn(p.x - __low2float(hh), p.y - __high2float(hh));
    h = h2u(hh);
    l = h2u(ll);
}

#define GBAR256(id) asm volatile("bar.sync %0, 256;" :: "r"(id) : "memory")
#define CP_ASYNC16(dst, src) \
    asm volatile("cp.async.cg.shared.global [%0], [%1], 16;" :: "r"(dst), "l"(src))
#define CP_COMMIT() asm volatile("cp.async.commit_group;" ::: "memory")
#define CP_WAIT0()  asm volatile("cp.async.wait_group 0;" ::: "memory")

// ---------------------------------------------------------------------------
// Prep: w -> angle (fp16 hi/lo) and log|w| (fp16).
// ---------------------------------------------------------------------------
__global__ void ces_prep(const float* __restrict__ wr, const float* __restrict__ wi) {
    int idx = blockIdx.x * blockDim.x + threadIdx.x;
    if (idx >= 16384) return;
    float a = wr[idx], b = wi[idx];
    float la = 0.5f * logf(fmaf(a, a, b * b));
    float an = atan2f(b, a);
    __half anh = __float2half_rn(an);
    __half anl = __float2half_rn(an - __half2float(anh));
    g_W[0 * 16384 + idx] = anh;                   // angH
    g_W[1 * 16384 + idx] = anl;                   // angL
    g_W[2 * 16384 + idx] = __float2half_rn(la);   // logH
}

// ---------------------------------------------------------------------------
// 16 warps = 4 groups x 4. Group g: row-block rb=g>>1 (64 rows), N-half nh=g&1.
// Within group: wm = lwid&1 (32 rows), wn = lwid>>1 (32 cols).
// ---------------------------------------------------------------------------
__global__ void __launch_bounds__(512, 1)
ces_main(const float* __restrict__ x, const float* __restrict__ bias,
         float* __restrict__ out) {
    extern __shared__ char smem[];
    const uint32_t sb = smem_u32(smem);
    const int tid   = threadIdx.x;
    const int lane  = tid & 31;
    const int wid   = tid >> 5;
    const int g     = wid >> 2;
    const int lwid  = wid & 3;
    const int rb    = g >> 1;         // row-block 0/1
    const int nh    = g & 1;          // N-half
    const int wm    = lwid & 1;
    const int wn    = lwid >> 1;
    const int rbtid = tid & 255;      // thread id within row-block (8 warps)

    const uint32_t xb = sb + (uint32_t)rb * 34816u;

    // ---- prologue: stage first tile's x (per row-block, 256 threads,
    //      64 rows x 128 f32 = 2048 chunks of 16B) ----
    int tile = blockIdx.x * 2 + rb;
    if (tile < N_TILES) {
        const float* src = x + (size_t)tile * 64 * 128;
        #pragma unroll
        for (int j = 0; j < 8; ++j) {
            int chunk = j * 256 + rbtid;            // 0..2047
            CP_ASYNC16(xb + (uint32_t)(chunk >> 5) * 544u + (uint32_t)(chunk & 31) * 16u,
                       src + (size_t)(chunk >> 5) * 128 + (chunk & 31) * 4);
        }
        CP_COMMIT();
    }

    // ---- copy W (3 x 128 x 128 fp16) into padded smem ----
    for (int r = tid; r < 384; r += 512) {
        const uint4* srcw = (const uint4*)(g_W + r * 128);
        uint4* dst = (uint4*)(smem + OFF_W + ((uint32_t)(r >> 7) * 17408u +
                                              (uint32_t)(r & 127) * LDS_STRIDE) * 2u);
        #pragma unroll
        for (int j = 0; j < 16; ++j) dst[j] = srcw[j];
    }
    if (tid < 128) ((float*)(smem + OFF_BIAS))[tid] = bias[tid];
    CP_WAIT0();
    __syncthreads();

    // A-side LDS base (f32): row = wm*32 + (lane>>2), col pair (lane&3)*2
    const uint32_t a_lds = xb +
        ((uint32_t)(wm * 32 + (lane >> 2)) * LDS_STRIDE + (uint32_t)((lane & 3) * 2)) * 4u;
    const uint32_t MI_X = 16u * LDS_STRIDE * 4u;
    const uint32_t R8_X = 8u * LDS_STRIDE * 4u;

    // B-side ldmatrix bases (fp16): col base nh*64 + wn*32
    const int colbase = nh * 64 + wn * 32;
    const uint32_t boff = ((uint32_t)(colbase + ((lane & 7) | ((lane & 16) >> 1))) * LDS_STRIDE +
                          (uint32_t)(lane & 8)) * 2u;
    const uint32_t MI_W = 16u * LDS_STRIDE * 2u;
    const uint32_t wbA = sb + OFF_W + boff;           // angH
    const uint32_t wbL = wbA + 34816u;                // angL
    const uint32_t wbG = wbA + 69632u;                // logH

    const int bar_id = rb + 1;

    for (; tile < N_TILES; tile += 2 * GRID_CTAS) {
        float acc[2][2][4][4];   // [mat(log/ang)][mi][nc][4]
        #pragma unroll
        for (int m = 0; m < 2; ++m)
            #pragma unroll
            for (int i = 0; i < 2; ++i)
                #pragma unroll
                for (int n = 0; n < 4; ++n)
                    #pragma unroll
                    for (int q = 0; q < 4; ++q) acc[m][i][n][q] = 0.f;

        // ---- fused k-loop ----
        #pragma unroll
        for (int k = 0; k < 8; ++k) {
            const uint32_t kw = (uint32_t)k * 32u;   // W: 16 fp16
            const uint32_t kx = (uint32_t)k * 64u;   // X: 16 f32

            // A fragments: LDS f32 pairs -> fp16 hi/lo
            uint32_t ah[2][4], al[2][4];
            #pragma unroll
            for (int mi = 0; mi < 2; ++mi) {
                const uint32_t ab = a_lds + (uint32_t)mi * MI_X + kx;
                float2 p0, p1, p2, p3;
                lds64(p0, ab);
                lds64(p1, ab + R8_X);
                lds64(p2, ab + 32u);
                lds64(p3, ab + R8_X + 32u);
                cvt_hl(p0, ah[mi][0], al[mi][0]);
                cvt_hl(p1, ah[mi][1], al[mi][1]);
                cvt_hl(p2, ah[mi][2], al[mi][2]);
                cvt_hl(p3, ah[mi][3], al[mi][3]);
            }

            // angH (live across passes 1 and 3)
            uint32_t bA[2][4];
            ldsm_x4(bA[0], wbA + kw);
            ldsm_x4(bA[1], wbA + MI_W + kw);

            // pass 1: ang += xh * angH
            #pragma unroll
            for (int h = 0; h < 2; ++h)
                #pragma unroll
                for (int q = 0; q < 2; ++q) {
                    mma16816(acc[1][0][h * 2 + q], ah[0], bA[h][2 * q], bA[h][2 * q + 1]);
                    mma16816(acc[1][1][h * 2 + q], ah[1], bA[h][2 * q], bA[h][2 * q + 1]);
                }

            // pass 2: log += xh * logH
            {
                uint32_t bG[2][4];
                ldsm_x4(bG[0], wbG + kw);
                ldsm_x4(bG[1], wbG + MI_W + kw);
                #pragma unroll
                for (int h = 0; h < 2; ++h)
                    #pragma unroll
                    for (int q = 0; q < 2; ++q) {
                        mma16816(acc[0][0][h * 2 + q], ah[0], bG[h][2 * q], bG[h][2 * q + 1]);
                        mma16816(acc[0][1][h * 2 + q], ah[1], bG[h][2 * q], bG[h][2 * q + 1]);
                    }
            }

            // pass 3: ang += xl * angH
            #pragma unroll
            for (int h = 0; h < 2; ++h)
                #pragma unroll
                for (int q = 0; q < 2; ++q) {
                    mma16816(acc[1][0][h * 2 + q], al[0], bA[h][2 * q], bA[h][2 * q + 1]);
                    mma16816(acc[1][1][h * 2 + q], al[1], bA[h][2 * q], bA[h][2 * q + 1]);
                }

            // pass 4: ang += xh * angL
            {
                uint32_t bL[2][4];
                ldsm_x4(bL[0], wbL + kw);
                ldsm_x4(bL[1], wbL + MI_W + kw);
                #pragma unroll
                for (int h = 0; h < 2; ++h)
                    #pragma unroll
                    for (int q = 0; q < 2; ++q) {
                        mma16816(acc[1][0][h * 2 + q], ah[0], bL[h][2 * q], bL[h][2 * q + 1]);
                        mma16816(acc[1][1][h * 2 + q], ah[1], bL[h][2 * q], bL[h][2 * q + 1]);
                    }
            }
        }

        GBAR256(bar_id);   // all 8 row-block warps done reading X[rb]

        // ---- stage next tile's x (latency hidden under epilogue) ----
        {
            int nxt = tile + 2 * GRID_CTAS;
            if (nxt < N_TILES) {
                const float* src = x + (size_t)nxt * 64 * 128;
                #pragma unroll
                for (int j = 0; j < 8; ++j) {
                    int chunk = j * 256 + rbtid;
                    CP_ASYNC16(xb + (uint32_t)(chunk >> 5) * 544u + (uint32_t)(chunk & 31) * 16u,
                               src + (size_t)(chunk >> 5) * 128 + (chunk & 31) * 4);
                }
                CP_COMMIT();
            }
        }

        // ---- epilogue: out = cos(ang + bias) * exp(log) ----
        #pragma unroll
        for (int mi = 0; mi < 2; ++mi) {
            size_t r0 = (size_t)tile * 64 + wm * 32 + mi * 16 + (lane >> 2);
            float* p0 = out + r0 * 128 + colbase + 2 * (lane & 3);
            #pragma unroll
            for (int nc = 0; nc < 4; ++nc) {
                float2 bb;
                lds64(bb, sb + OFF_BIAS +
                          (uint32_t)(colbase + nc * 8 + 2 * (lane & 3)) * 4u);
                const float* A = acc[1][mi][nc];
                const float* G = acc[0][mi][nc];
                float2 o0, o1;
                o0.x = __cosf(A[0] + bb.x) * __expf(G[0]);
                o0.y = __cosf(A[1] + bb.y) * __expf(G[1]);
                o1.x = __cosf(A[2] + bb.x) * __expf(G[2]);
                o1.y = __cosf(A[3] + bb.y) * __expf(G[3]);
                *(float2*)(p0 + nc * 8) = o0;
                *(float2*)(p0 + nc * 8 + 8 * 128) = o1;
            }
        }

        CP_WAIT0();
        GBAR256(bar_id);   // X[rb] refilled for the whole row-block
    }
}

// ---------------------------------------------------------------------------
extern "C" void kernel_launch(void* const* d_in, const int* in_sizes, int n_in,
                              void* d_out, int out_size) {
    const float* x    = (const float*)d_in[0];
    const float* wr   = (const float*)d_in[1];
    const float* wi   = (const float*)d_in[2];
    const float* bias = (const float*)d_in[3];
    float* out = (float*)d_out;
    (void)in_sizes; (void)n_in; (void)out_size;

    cudaFuncSetAttribute(ces_main, cudaFuncAttributeMaxDynamicSharedMemorySize,
                         (int)SMEM_BYTES);

    ces_prep<<<64, 256>>>(wr, wi);
    ces_main<<<GRID_CTAS, 512, SMEM_BYTES>>>(x, bias, out);
}